// round 2
// baseline (speedup 1.0000x reference)
#include <cuda_runtime.h>

// Problem: B=32, T=256, D=64.
// real, imag: [B, T, D] float32.
// out: [2, T, B, D, D] float32.
//   out_real[t,b,p,q] = r_p*r_q + i_p*i_q
//   out_imag[t,b,p,q] = i_p*r_q - r_p*i_q
// where r = real[b, t, :], i = imag[b, t, :].

#define PB 32
#define PT 256
#define PD 64
#define TILE (PD * PD)            // 4096 floats per (t,b) per component
#define IMAG_OFF ((size_t)PT * PB * TILE)

__global__ __launch_bounds__(256, 8)
void qouterc_kernel(const float* __restrict__ real,
                    const float* __restrict__ imag,
                    float* __restrict__ out)
{
    const int tb = blockIdx.x;          // tb = t*B + b  (matches out layout)
    const int t  = tb >> 5;             // / 32
    const int b  = tb & 31;

    __shared__ float rs[PD];
    __shared__ float is[PD];

    const int tid = threadIdx.x;

    // Input layout [B, T, D]: element (b, t, d) at b*T*D + t*D + d
    const size_t in_base = (size_t)b * (PT * PD) + (size_t)t * PD;
    if (tid < PD)
        rs[tid] = real[in_base + tid];
    else if (tid < 2 * PD)
        is[tid - PD] = imag[in_base + (tid - PD)];
    __syncthreads();

    // Output tile for this (t,b): 4096 floats = 1024 float4.
    // Thread mapping: float4 index n4 = j*256 + tid  (j = 0..3)
    //   -> each warp's store instruction covers a contiguous 512B span.
    float* out_r = out + (size_t)tb * TILE;
    float* out_i = out + IMAG_OFF + (size_t)tb * TILE;

    #pragma unroll
    for (int j = 0; j < 4; ++j) {
        const int n4 = j * 256 + tid;       // float4 index within tile, 0..1023
        const int p  = n4 >> 4;             // row (16 float4 per row of 64)
        const int q  = (n4 & 15) << 2;      // starting column

        const float rp = rs[p];
        const float ip = is[p];

        float4 vr, vi;
        {
            float rq, iq;
            rq = rs[q + 0]; iq = is[q + 0];
            vr.x = rp * rq + ip * iq;  vi.x = ip * rq - rp * iq;
            rq = rs[q + 1]; iq = is[q + 1];
            vr.y = rp * rq + ip * iq;  vi.y = ip * rq - rp * iq;
            rq = rs[q + 2]; iq = is[q + 2];
            vr.z = rp * rq + ip * iq;  vi.z = ip * rq - rp * iq;
            rq = rs[q + 3]; iq = is[q + 3];
            vr.w = rp * rq + ip * iq;  vi.w = ip * rq - rp * iq;
        }

        // Streaming stores: 256 MiB write-once output, keep it out of L2's way.
        __stcs(reinterpret_cast<float4*>(out_r) + n4, vr);
        __stcs(reinterpret_cast<float4*>(out_i) + n4, vi);
    }
}

extern "C" void kernel_launch(void* const* d_in, const int* in_sizes, int n_in,
                              void* d_out, int out_size)
{
    const float* real = (const float*)d_in[0];
    const float* imag = (const float*)d_in[1];
    float* out = (float*)d_out;

    // One CTA per (t, b) pair: T*B = 8192 CTAs, 256 threads each.
    qouterc_kernel<<<PT * PB, 256>>>(real, imag, out);
}